// round 2
// baseline (speedup 1.0000x reference)
#include <cuda_runtime.h>

#define HID 50
#define NPTS 8192
#define NPARA 5000
#define WARPS_PER_BLOCK 8
#define THREADS (WARPS_PER_BLOCK * 32)
#define NBLOCKS (NPTS / WARPS_PER_BLOCK)

// shared layout (floats)
#define OFF_WIN 0
#define OFF_BIN 150
#define OFF_WH  200
#define OFF_BH  10200
#define OFF_WO  10400
#define OFF_BO  10500
#define OFF_STATE 10504                 // byte offset 42016, 8B aligned
#define STATE_STRIDE 400                // 50 units * 8 floats per warp (1600B, 8B aligned)
#define OFF_OUT8 (OFF_STATE + WARPS_PER_BLOCK * STATE_STRIDE)
#define OFF_PART (OFF_OUT8 + WARPS_PER_BLOCK * 8)
#define OFF_FLAG (OFF_PART + WARPS_PER_BLOCK * 6)
#define SMEM_FLOATS (OFF_FLAG + 1)
#define SMEM_BYTES (SMEM_FLOATS * 4)    // ~55.3 KB -> 4 blocks/SM

typedef unsigned long long u64;

__device__ double g_sums[6];
__device__ unsigned int g_ticket;

__device__ __forceinline__ u64 pack2(float lo, float hi) {
    u64 r; asm("mov.b64 %0, {%1, %2};" : "=l"(r) : "f"(lo), "f"(hi)); return r;
}
__device__ __forceinline__ void unpack2(u64 v, float& lo, float& hi) {
    asm("mov.b64 {%0, %1}, %2;" : "=f"(lo), "=f"(hi) : "l"(v));
}
// d.lo += a.lo*b.lo ; d.hi += a.hi*b.hi   (SASS FFMA2, PTX-only)
__device__ __forceinline__ void ffma2(u64& d, u64 a, u64 b) {
    asm("fma.rn.f32x2 %0, %1, %2, %0;" : "+l"(d) : "l"(a), "l"(b));
}

// tanh(z) and sech^2(z): r = 1/(e^{2z}+1); h = 1-2r; 1-h^2 = 4r(1-r)
__device__ __forceinline__ void tanh_s(float z, float& h, float& s) {
    float e = __expf(2.0f * z);
    float r = __fdividef(1.0f, e + 1.0f);
    h = 1.0f - 2.0f * r;
    s = 4.0f * r * (1.0f - r);
}

__global__ void __launch_bounds__(THREADS) pinn_kernel(
    const float* __restrict__ x,
    const float* __restrict__ para,
    const float* __restrict__ W_in, const float* __restrict__ b_in,
    const float* __restrict__ W_hid, const float* __restrict__ b_hid,
    const float* __restrict__ W_out, const float* __restrict__ b_out,
    float* __restrict__ out)
{
    extern __shared__ float sm[];
    const int tid = threadIdx.x;

    for (int i = tid; i < 150;   i += THREADS) sm[OFF_WIN + i] = W_in[i];
    for (int i = tid; i < 50;    i += THREADS) sm[OFF_BIN + i] = b_in[i];
    for (int i = tid; i < 10000; i += THREADS) sm[OFF_WH  + i] = W_hid[i];
    for (int i = tid; i < 200;   i += THREADS) sm[OFF_BH  + i] = b_hid[i];
    for (int i = tid; i < 100;   i += THREADS) sm[OFF_WO  + i] = W_out[i];
    if (tid < 2) sm[OFF_BO + tid] = b_out[tid];
    __syncthreads();

    const int warp = tid >> 5;
    const int lane = tid & 31;
    const int point = blockIdx.x * WARPS_PER_BLOCK + warp;
    float* st = sm + OFF_STATE + warp * STATE_STRIDE;
    const u64* stu = (const u64*)st;

    const float x0 = x[point * 3 + 0];
    const float x1 = x[point * 3 + 1];
    const float x2 = x[point * 3 + 2];

    // ---- input layer: z = x @ W_in + b_in; first derivs = W_in rows; z'' = 0
    #pragma unroll
    for (int o = 0; o < 2; o++) {
        int j = lane + 32 * o;
        if (j < HID) {
            float w0 = sm[OFF_WIN + j];
            float w1 = sm[OFF_WIN + 50 + j];
            float w2 = sm[OFF_WIN + 100 + j];
            float z = sm[OFF_BIN + j] + x0 * w0 + x1 * w1 + x2 * w2;
            float h, s; tanh_s(z, h, s);
            float d0  = s * w0;
            float dd0 = -2.0f * h * d0 * w0;
            float d1  = s * w1;
            float dd1 = -2.0f * h * d1 * w1;
            float d2  = s * w2;
            u64* pw = (u64*)(st + j * 8);
            pw[0] = pack2(h, d0); pw[1] = pack2(dd0, d1); pw[2] = pack2(dd1, d2);
        }
    }
    __syncwarp();

    // ---- 4 hidden layers: 6-channel matvec (f32x2-packed) + tanh chain rule
    const int j1 = lane;
    const int j2 = lane + 32;
    const bool has2 = (j2 < HID);

    for (int l = 0; l < 4; l++) {
        const float* Wl = sm + OFF_WH + l * 2500;
        const float* bl = sm + OFF_BH + l * 50;

        u64 P0a = pack2(bl[j1], 0.0f), P1a = 0ull, P2a = 0ull;  // {z,zx} {zxx,zy} {zyy,zt}
        u64 P0b = pack2(bl[j2], 0.0f), P1b = 0ull, P2b = 0ull;  // j2 garbage lanes unused

        #pragma unroll
        for (int k = 0; k < HID; k++) {
            u64 h01 = stu[k * 4 + 0];   // {h, dx}   (broadcast)
            u64 h23 = stu[k * 4 + 1];   // {dxx, dy}
            u64 h45 = stu[k * 4 + 2];   // {dyy, dt}
            float w1 = Wl[k * 50 + j1];
            float w2 = Wl[k * 50 + j2];         // may read junk for lanes !has2 (in-bounds)
            u64 ww1 = pack2(w1, w1);
            u64 ww2 = pack2(w2, w2);
            ffma2(P0a, h01, ww1); ffma2(P1a, h23, ww1); ffma2(P2a, h45, ww1);
            ffma2(P0b, h01, ww2); ffma2(P1b, h23, ww2); ffma2(P2b, h45, ww2);
        }
        __syncwarp();   // all reads of old state complete before overwrite
        {
            float z, zx, zxx, zy, zyy, zt;
            unpack2(P0a, z, zx); unpack2(P1a, zxx, zy); unpack2(P2a, zyy, zt);
            float h, s; tanh_s(z, h, s);
            float d0  = s * zx;
            float dd0 = fmaf(-2.0f * h * d0, zx, s * zxx);
            float d1  = s * zy;
            float dd1 = fmaf(-2.0f * h * d1, zy, s * zyy);
            float d2  = s * zt;
            u64* pw = (u64*)(st + j1 * 8);
            pw[0] = pack2(h, d0); pw[1] = pack2(dd0, d1); pw[2] = pack2(dd1, d2);
        }
        if (has2) {
            float z, zx, zxx, zy, zyy, zt;
            unpack2(P0b, z, zx); unpack2(P1b, zxx, zy); unpack2(P2b, zyy, zt);
            float h, s; tanh_s(z, h, s);
            float d0  = s * zx;
            float dd0 = fmaf(-2.0f * h * d0, zx, s * zxx);
            float d1  = s * zy;
            float dd1 = fmaf(-2.0f * h * d1, zy, s * zyy);
            float d2  = s * zt;
            u64* pw = (u64*)(st + j2 * 8);
            pw[0] = pack2(h, d0); pw[1] = pack2(dd0, d1); pw[2] = pack2(dd1, d2);
        }
        __syncwarp();
    }

    // ---- output layer: channels {0,2,4,5} x outputs {u,v} = 8 dot products
    if (lane < 8) {
        int ch = (lane >> 1) * 2;        // 0,2,4,6
        if (ch == 6) ch = 5;             // -> 0,2,4,5
        int o = lane & 1;
        float acc0 = (ch == 0) ? sm[OFF_BO + o] : 0.0f;
        float acc1 = 0.0f;
        #pragma unroll
        for (int k = 0; k < HID; k += 2) {
            acc0 = fmaf(st[k * 8 + ch],       sm[OFF_WO + k * 2 + o],       acc0);
            acc1 = fmaf(st[(k + 1) * 8 + ch], sm[OFF_WO + (k + 1) * 2 + o], acc1);
        }
        sm[OFF_OUT8 + warp * 8 + lane] = acc0 + acc1;
    }
    __syncwarp();

    if (lane == 0) {
        const float* o8 = sm + OFF_OUT8 + warp * 8;
        float u   = o8[0], v   = o8[1];
        float uxx = o8[2], vxx = o8[3];
        float uyy = o8[4], vyy = o8[5];
        float ut  = o8[6], vt  = o8[7];
        float Q  = u * u + v * v;
        float A1 = vt - 0.5f * uxx - 0.5f * vyy - Q * u + v;
        float A2 = ut + 0.5f * vxx - 0.5f * uyy + Q * v + u;
        float B1 = uyy, B2 = vyy;
        float C1 = Q * v, C2 = Q * u;
        float* pp = sm + OFF_PART + warp * 6;
        pp[0] = A1 * A1 + A2 * A2;
        pp[1] = B1 * B1 + B2 * B2;
        pp[2] = C1 * C1 + C2 * C2;
        pp[3] = A2 * B2 - A1 * B1;
        pp[4] = A1 * C1 + A2 * C2;
        pp[5] = B1 * C1 - B2 * C2;
    }
    __syncthreads();

    if (tid < 6) {
        double s = 0.0;
        #pragma unroll
        for (int w = 0; w < WARPS_PER_BLOCK; w++)
            s += (double)sm[OFF_PART + w * 6 + tid];
        atomicAdd(&g_sums[tid], s);
    }
    __syncthreads();

    // ---- last-block-done: fused finalize (removes 2 extra launches)
    if (tid == 0) {
        __threadfence();
        unsigned t = atomicAdd(&g_ticket, 1u);
        ((unsigned*)sm)[OFF_FLAG] = (t == (unsigned)(gridDim.x - 1)) ? 1u : 0u;
    }
    __syncthreads();

    if (((unsigned*)sm)[OFF_FLAG]) {
        double s0 = g_sums[0], s1 = g_sums[1], s2 = g_sums[2];
        double s3 = g_sums[3], s4 = g_sums[4], s5 = g_sums[5];
        for (int p = tid; p < NPARA; p += THREADS) {
            double a = (double)para[p * 3 + 0];
            double c = (double)para[p * 3 + 2];
            double r = s0 + 0.25 * a * a * s1 + c * c * s2
                     + a * s3 - 2.0 * c * s4 + a * c * s5;
            out[p] = (float)(r * (1.0 / (double)NPTS));
        }
        __syncthreads();
        if (tid == 0) {                 // reset for next graph replay
            g_ticket = 0u;
            #pragma unroll
            for (int i = 0; i < 6; i++) g_sums[i] = 0.0;
        }
    }
}

extern "C" void kernel_launch(void* const* d_in, const int* in_sizes, int n_in,
                              void* d_out, int out_size) {
    const float* x     = (const float*)d_in[0];
    const float* para  = (const float*)d_in[1];
    const float* W_in  = (const float*)d_in[2];
    const float* b_in  = (const float*)d_in[3];
    const float* W_hid = (const float*)d_in[4];
    const float* b_hid = (const float*)d_in[5];
    const float* W_out = (const float*)d_in[6];
    const float* b_out = (const float*)d_in[7];
    float* out = (float*)d_out;

    cudaFuncSetAttribute(pinn_kernel, cudaFuncAttributeMaxDynamicSharedMemorySize, SMEM_BYTES);
    pinn_kernel<<<NBLOCKS, THREADS, SMEM_BYTES>>>(
        x, para, W_in, b_in, W_hid, b_hid, W_out, b_out, out);
}